// round 10
// baseline (speedup 1.0000x reference)
#include <cuda_runtime.h>
#include <cstdint>

#define BB 64
#define TT 1024
#define EE 300
#define HH 512
#define G4 2048
#define M_ROWS (BB*TT)

// ---------------- scratch (device globals; no allocations) ----------------
__device__ float    g_out1[(size_t)M_ROWS * EE];   // embeddings
__device__ float    g_zx[(size_t)M_ROWS * G4];     // zx = out1@Wx + b
__device__ uint32_t g_htf2[2][2][16384];           // [group][parity] h tf32 frag-major (32 rows)
__device__ float    g_c1[BB * 8 * 256];            // conv1 window t=6..13
__device__ float    g_c2[BB * HH];                 // conv2 at t=9
__device__ unsigned g_flags2[2][128 * 32];         // per-group per-CTA flags (128B stride)

// ---------------- tf32 mma.sync helpers ----------------
__device__ __forceinline__ uint32_t f2tf32(float f) {
    uint32_t r; asm("cvt.rna.tf32.f32 %0, %1;" : "=r"(r) : "f"(f)); return r;
}
__device__ __forceinline__ void mma16n8k8(float* d, const uint32_t* a, const uint32_t* b) {
    asm volatile("mma.sync.aligned.m16n8k8.row.col.f32.tf32.tf32.f32 "
        "{%0,%1,%2,%3}, {%4,%5,%6,%7}, {%8,%9}, {%0,%1,%2,%3};"
        : "+f"(d[0]), "+f"(d[1]), "+f"(d[2]), "+f"(d[3])
        : "r"(a[0]), "r"(a[1]), "r"(a[2]), "r"(a[3]), "r"(b[0]), "r"(b[1]));
}

// fragment-layout index for 32-row group: (b_local 0..31, col 0..511)
__device__ __forceinline__ int htf_idx32(int bl, int col) {
    int mtv = bl >> 4, g2 = bl & 7, hi = (bl >> 3) & 1;
    int ks = col >> 3, khi = (col >> 2) & 1, kq = col & 3;
    return (((mtv * 64 + ks) << 7) + (g2 << 4) + (kq << 2) + khi * 2 + hi);
}

// ---------------- init: h0 -> g_htf2[g][0], reset flags ----------
__global__ void init_kernel(const float* __restrict__ h0) {
    int i = blockIdx.x * blockDim.x + threadIdx.x;
    if (i < BB * HH) {
        int b = i >> 9, col = i & 511;
        g_htf2[b >> 5][0][htf_idx32(b & 31, col)] = f2tf32(h0[i]);
    }
    if (i < 128 * 32) { g_flags2[0][i] = 0u; g_flags2[1][i] = 0u; }
}

// ---------------- embedding gather ----------------
__global__ void embed_kernel(const int* __restrict__ idx, const float* __restrict__ table) {
    long gid = (long)blockIdx.x * blockDim.x + threadIdx.x;
    const long total = (long)M_ROWS * 75;
    if (gid >= total) return;
    long r = gid / 75;
    int  e4 = (int)(gid % 75);
    int row = idx[r];
    ((float4*)g_out1)[r * 75 + e4] = ((const float4*)table)[(long)row * 75 + e4];
}

// ---------------- zx GEMM via mma.sync tf32 (proven) -------------
#define LDA 136
__global__ __launch_bounds__(256) void zx_gemm_tc(const float* __restrict__ Wx,
                                                  const float* __restrict__ bias) {
    __shared__ uint32_t As[32][LDA];
    __shared__ uint32_t Bs[32][LDA];

    const int tid  = threadIdx.x;
    const int wid  = tid >> 5;
    const int lane = tid & 31;
    const int gid  = lane >> 2;
    const int tig  = lane & 3;
    const int wm   = wid >> 2;
    const int wn   = wid & 3;
    const int bm = blockIdx.y * 128;
    const int bn = blockIdx.x * 128;

    float acc[4][4][4];
#pragma unroll
    for (int i = 0; i < 4; i++)
#pragma unroll
        for (int j = 0; j < 4; j++)
#pragma unroll
            for (int c = 0; c < 4; c++) acc[i][j][c] = 0.f;

    for (int k0 = 0; k0 < 320; k0 += 32) {
        {
            int row = tid >> 1;
            int kh  = (tid & 1) * 16;
            const float* src = &g_out1[(size_t)(bm + row) * EE + k0 + kh];
#pragma unroll
            for (int q = 0; q < 4; q++) {
                int kc = k0 + kh + q * 4;
                float4 v = make_float4(0.f, 0.f, 0.f, 0.f);
                if (kc + 3 < EE) v = *(const float4*)(src + q * 4);
                else {
                    if (kc + 0 < EE) v.x = src[q * 4 + 0];
                    if (kc + 1 < EE) v.y = src[q * 4 + 1];
                    if (kc + 2 < EE) v.z = src[q * 4 + 2];
                    if (kc + 3 < EE) v.w = src[q * 4 + 3];
                }
                As[kh + q * 4 + 0][row] = f2tf32(v.x);
                As[kh + q * 4 + 1][row] = f2tf32(v.y);
                As[kh + q * 4 + 2][row] = f2tf32(v.z);
                As[kh + q * 4 + 3][row] = f2tf32(v.w);
            }
        }
        {
            int k  = tid >> 3;
            int nq = (tid & 7) * 16;
#pragma unroll
            for (int q = 0; q < 4; q++) {
                float4 v = make_float4(0.f, 0.f, 0.f, 0.f);
                if (k0 + k < EE) v = *(const float4*)&Wx[(size_t)(k0 + k) * G4 + bn + nq + q * 4];
                Bs[k][nq + q * 4 + 0] = f2tf32(v.x);
                Bs[k][nq + q * 4 + 1] = f2tf32(v.y);
                Bs[k][nq + q * 4 + 2] = f2tf32(v.z);
                Bs[k][nq + q * 4 + 3] = f2tf32(v.w);
            }
        }
        __syncthreads();

#pragma unroll
        for (int s = 0; s < 4; s++) {
            const int ks = s * 8;
            uint32_t af[4][4], bf[4][2];
#pragma unroll
            for (int mt = 0; mt < 4; mt++) {
                int mb = wm * 64 + mt * 16 + gid;
                af[mt][0] = As[ks + tig][mb];
                af[mt][1] = As[ks + tig][mb + 8];
                af[mt][2] = As[ks + tig + 4][mb];
                af[mt][3] = As[ks + tig + 4][mb + 8];
            }
#pragma unroll
            for (int nt = 0; nt < 4; nt++) {
                int nb = wn * 32 + nt * 8 + gid;
                bf[nt][0] = Bs[ks + tig][nb];
                bf[nt][1] = Bs[ks + tig + 4][nb];
            }
#pragma unroll
            for (int mt = 0; mt < 4; mt++)
#pragma unroll
                for (int nt = 0; nt < 4; nt++)
                    mma16n8k8(acc[mt][nt], af[mt], bf[nt]);
        }
        __syncthreads();
    }

#pragma unroll
    for (int mt = 0; mt < 4; mt++) {
        int r0 = bm + wm * 64 + mt * 16 + gid;
#pragma unroll
        for (int nt = 0; nt < 4; nt++) {
            int ncol = bn + wn * 32 + nt * 8 + tig * 2;
            float2 bv = *(const float2*)&bias[ncol];
            float2 lo = make_float2(acc[mt][nt][0] + bv.x, acc[mt][nt][1] + bv.y);
            float2 hi = make_float2(acc[mt][nt][2] + bv.x, acc[mt][nt][3] + bv.y);
            *(float2*)&g_zx[(size_t)r0 * G4 + ncol] = lo;
            *(float2*)&g_zx[(size_t)(r0 + 8) * G4 + ncol] = hi;
        }
    }
}

// ---------------- conv1: 512 CTAs, one output t per CTA ----------------
__global__ __launch_bounds__(256) void conv1_kernel(const float* __restrict__ W1,
                                                    const float* __restrict__ b1) {
    int bb = blockIdx.x >> 3;
    int th = blockIdx.x & 7;
    __shared__ float xs[10 * EE];
    int tid = threadIdx.x;
    for (int i = tid; i < 10 * EE; i += 256) {
        int rt = i / EE, e = i % EE;
        xs[rt * EE + e] = g_out1[((long)(bb * TT) + 2 + th + rt) * EE + e];
    }
    __syncthreads();
    int m = tid;
    float acc = 0.f;
#pragma unroll 5
    for (int i = 0; i < 10 * EE; i++)
        acc += xs[i] * W1[(size_t)i * 256 + m];
    float v = acc + b1[m];
    v = v > 0.f ? v : 0.f;
    g_c1[(bb * 8 + th) * 256 + m] = v;
}

// ---------------- conv2 at t=9 ----------------
__global__ __launch_bounds__(512) void conv2_kernel(const float* __restrict__ W2,
                                                    const float* __restrict__ b2) {
    int bb = blockIdx.x;
    __shared__ float cs[8 * 256];
    int tid = threadIdx.x;
    for (int i = tid; i < 2048; i += 512) cs[i] = g_c1[bb * 2048 + i];
    __syncthreads();
    int n = tid;
    float acc = 0.f;
#pragma unroll 4
    for (int i = 0; i < 2048; i++)
        acc += cs[i] * W2[(size_t)i * HH + n];
    float v = acc + b2[n];
    v = v > 0.f ? v : 0.f;
    g_c2[bb * HH + n] = v;
}

// ---------------- res9 add ----------------
__global__ void res9_kernel(float* __restrict__ out_res9) {
    int i = blockIdx.x * blockDim.x + threadIdx.x;
    if (i < BB * HH) out_res9[i] += g_c2[i];
}

// ---------------- persistent masked LSTM: 2-group pipelined recurrence ------
// Groups A (b 0-31) / B (b 32-63) alternate; each group's flag poll is hidden
// behind the other group's compute. 8 warps = mt(2) x nt(2) x kh(2).
#define LC 128

__device__ __forceinline__ float sigf(float x) { return 1.f / (1.f + __expf(-x)); }

__device__ __forceinline__ void poll_flags(volatile unsigned* vf, unsigned tgt, int lane) {
    bool ok;
    do {
        unsigned v0 = vf[lane * 32];
        unsigned v1 = vf[(lane + 32) * 32];
        unsigned v2 = vf[(lane + 64) * 32];
        unsigned v3 = vf[(lane + 96) * 32];
        ok = (v0 >= tgt) && (v1 >= tgt) && (v2 >= tgt) && (v3 >= tgt);
    } while (!__all_sync(0xffffffffu, ok));
    asm volatile("fence.acq_rel.gpu;" ::: "memory");
}

__global__ __launch_bounds__(256, 1) void lstm_kernel(const float* __restrict__ Wh,
                                                      const float* __restrict__ c0,
                                                      const float* __restrict__ h0,
                                                      const int* __restrict__ in_seq,
                                                      float* __restrict__ out_enc,
                                                      float* __restrict__ out_res9,
                                                      float* __restrict__ out_c) {
    extern __shared__ uint32_t smemu[];
    uint32_t* fragA = smemu;            // 16384 u32 (64 KB)
    uint32_t* fragB = smemu + 16384;    // 16384 u32
    float*    red   = (float*)(smemu + 32768);   // 16*2*33 = 1056 floats

    const int tid  = threadIdx.x;
    const int warp = tid >> 5;
    const int lane = tid & 31;
    const int gid  = lane >> 2;
    const int tig  = lane & 3;
    const int mt   = (warp >> 2) & 1;
    const int nt   = (warp >> 1) & 1;
    const int kh   = warp & 1;
    const int lt   = nt * 32 + lane;          // 0..63 within (mt,kh) pair
    const int pairBar = 4 + mt * 2 + kh;
    const int j0   = blockIdx.x * 4;

    // gate-thread identity (tid < 128)
    const int b32 = tid & 31;
    const int jc  = (tid >> 5) & 3;
    const int col = j0 + jc;
    const int my_idx = htf_idx32(b32, col);

    // ---- Wh fragments -> registers (loop-invariant): K-half per warp ----
    uint32_t bfr[32][2];
    {
        int c  = nt * 8 + gid;
        int g  = c >> 2, jj = c & 3;
        int wcol = j0 + jj + g * 512;
        int kb = kh * 256;
#pragma unroll 32
        for (int ks = 0; ks < 32; ks++) {
            bfr[ks][0] = f2tf32(Wh[(size_t)(kb + ks * 8 + tig) * G4 + wcol]);
            bfr[ks][1] = f2tf32(Wh[(size_t)(kb + ks * 8 + tig + 4) * G4 + wcol]);
        }
    }

    // ---- gate state (registers): both groups ----
    float cregA = 0.f, hregA = 0.f, cregB = 0.f, hregB = 0.f;
    float zA0 = 0, zA1 = 0, zA2 = 0, zA3 = 0, zB0 = 0, zB1 = 0, zB2 = 0, zB3 = 0;
    int mA = 0, mB = 0;
    if (tid < 128) {
        cregA = c0[b32 * HH + col];
        hregA = h0[b32 * HH + col];
        cregB = c0[(b32 + 32) * HH + col];
        hregB = h0[(b32 + 32) * HH + col];
        size_t za = ((size_t)b32 * TT) * G4 + col;
        size_t zbq = ((size_t)(b32 + 32) * TT) * G4 + col;
        zA0 = __ldg(&g_zx[za]);        zA1 = __ldg(&g_zx[za + 512]);
        zA2 = __ldg(&g_zx[za + 1024]); zA3 = __ldg(&g_zx[za + 1536]);
        zB0 = __ldg(&g_zx[zbq]);        zB1 = __ldg(&g_zx[zbq + 512]);
        zB2 = __ldg(&g_zx[zbq + 1024]); zB3 = __ldg(&g_zx[zbq + 1536]);
        mA = in_seq[b32 * TT];
        mB = in_seq[(b32 + 32) * TT];
    }
    __syncthreads();

    const int chunk = mt * 2048 + kh * 1024;        // uint4 offset of this pair's region
    const uint32_t* fbA = fragA + (mt * 64 + kh * 32) * 128 + lane * 4;
    const uint32_t* fbB = fragB + (mt * 64 + kh * 32) * 128 + lane * 4;

    for (int t = 0; t < TT; t++) {
        // ================= group A phase =================
        if (warp == 0 && t > 0) poll_flags(g_flags2[0], (unsigned)t, lane);
        __syncthreads();
        {   // copy own chunk of h_A(t-1)
            const uint4* src = (const uint4*)g_htf2[0][t & 1] + chunk;
            uint4* dst = (uint4*)fragA + chunk;
#pragma unroll 16
            for (int j = lt; j < 1024; j += 64) dst[j] = __ldcg(src + j);
        }
        asm volatile("bar.sync %0, 64;" :: "r"(pairBar) : "memory");

        {   // MMA over own K-half
            float acc[4] = {0.f, 0.f, 0.f, 0.f};
#pragma unroll 32
            for (int ks = 0; ks < 32; ks++) {
                uint32_t af[4];
                *(uint4*)af = *(const uint4*)(fbA + ks * 128);
                mma16n8k8(acc, af, bfr[ks]);
            }
            int c0i = nt * 8 + tig * 2;
            int r0  = mt * 16 + gid;
            red[((c0i    ) * 2 + kh) * 33 + r0]     = acc[0];
            red[((c0i + 1) * 2 + kh) * 33 + r0]     = acc[1];
            red[((c0i    ) * 2 + kh) * 33 + r0 + 8] = acc[2];
            red[((c0i + 1) * 2 + kh) * 33 + r0 + 8] = acc[3];
        }
        __syncthreads();

        if (tid < 128) {   // gates A
            float z0 = zA0 + red[((0 * 4 + jc) * 2) * 33 + b32] + red[((0 * 4 + jc) * 2 + 1) * 33 + b32];
            float z1 = zA1 + red[((1 * 4 + jc) * 2) * 33 + b32] + red[((1 * 4 + jc) * 2 + 1) * 33 + b32];
            float z2 = zA2 + red[((2 * 4 + jc) * 2) * 33 + b32] + red[((2 * 4 + jc) * 2 + 1) * 33 + b32];
            float z3 = zA3 + red[((3 * 4 + jc) * 2) * 33 + b32] + red[((3 * 4 + jc) * 2 + 1) * 33 + b32];
            float cn = sigf(z1) * cregA + sigf(z0) * tanhf(z2);
            float hn = sigf(z3) * tanhf(cn);
            if (mA == 0) { hn = hregA; cn = cregA; }
            cregA = cn; hregA = hn;
            __stcg(&g_htf2[0][(t & 1) ^ 1][my_idx], f2tf32(hn));
            out_enc[((size_t)b32 * TT + t) * HH + col] = hn;
            if (t == 9)      out_res9[b32 * HH + col] = hn;
            if (t == TT - 1) out_c[b32 * HH + col] = cn;
        }
        __syncthreads();
        if (tid == 0) {
            unsigned v = (unsigned)(t + 1);
            asm volatile("st.release.gpu.global.u32 [%0], %1;"
                         :: "l"(&g_flags2[0][blockIdx.x * 32]), "r"(v) : "memory");
        }

        // ================= group B phase =================
        if (warp == 0 && t > 0) poll_flags(g_flags2[1], (unsigned)t, lane);
        __syncthreads();
        {
            const uint4* src = (const uint4*)g_htf2[1][t & 1] + chunk;
            uint4* dst = (uint4*)fragB + chunk;
#pragma unroll 16
            for (int j = lt; j < 1024; j += 64) dst[j] = __ldcg(src + j);
        }
        asm volatile("bar.sync %0, 64;" :: "r"(pairBar) : "memory");

        {
            float acc[4] = {0.f, 0.f, 0.f, 0.f};
#pragma unroll 32
            for (int ks = 0; ks < 32; ks++) {
                uint32_t af[4];
                *(uint4*)af = *(const uint4*)(fbB + ks * 128);
                mma16n8k8(acc, af, bfr[ks]);
            }
            int c0i = nt * 8 + tig * 2;
            int r0  = mt * 16 + gid;
            red[((c0i    ) * 2 + kh) * 33 + r0]     = acc[0];
            red[((c0i + 1) * 2 + kh) * 33 + r0]     = acc[1];
            red[((c0i    ) * 2 + kh) * 33 + r0 + 8] = acc[2];
            red[((c0i + 1) * 2 + kh) * 33 + r0 + 8] = acc[3];
        }
        __syncthreads();

        if (tid < 128) {   // gates B + prefetch t+1 for both groups
            const int gb = b32 + 32;
            float z0 = zB0 + red[((0 * 4 + jc) * 2) * 33 + b32] + red[((0 * 4 + jc) * 2 + 1) * 33 + b32];
            float z1 = zB1 + red[((1 * 4 + jc) * 2) * 33 + b32] + red[((1 * 4 + jc) * 2 + 1) * 33 + b32];
            float z2 = zB2 + red[((2 * 4 + jc) * 2) * 33 + b32] + red[((2 * 4 + jc) * 2 + 1) * 33 + b32];
            float z3 = zB3 + red[((3 * 4 + jc) * 2) * 33 + b32] + red[((3 * 4 + jc) * 2 + 1) * 33 + b32];
            float cn = sigf(z1) * cregB + sigf(z0) * tanhf(z2);
            float hn = sigf(z3) * tanhf(cn);
            if (mB == 0) { hn = hregB; cn = cregB; }
            cregB = cn; hregB = hn;
            __stcg(&g_htf2[1][(t & 1) ^ 1][my_idx], f2tf32(hn));
            out_enc[((size_t)gb * TT + t) * HH + col] = hn;
            if (t == 9)      out_res9[gb * HH + col] = hn;
            if (t == TT - 1) out_c[gb * HH + col] = cn;

            if (t + 1 < TT) {
                size_t za = ((size_t)b32 * TT + (t + 1)) * G4 + col;
                size_t zbq = ((size_t)gb * TT + (t + 1)) * G4 + col;
                zA0 = __ldg(&g_zx[za]);        zA1 = __ldg(&g_zx[za + 512]);
                zA2 = __ldg(&g_zx[za + 1024]); zA3 = __ldg(&g_zx[za + 1536]);
                zB0 = __ldg(&g_zx[zbq]);        zB1 = __ldg(&g_zx[zbq + 512]);
                zB2 = __ldg(&g_zx[zbq + 1024]); zB3 = __ldg(&g_zx[zbq + 1536]);
                mA = in_seq[b32 * TT + t + 1];
                mB = in_seq[gb * TT + t + 1];
            }
        }
        __syncthreads();
        if (tid == 0) {
            unsigned v = (unsigned)(t + 1);
            asm volatile("st.release.gpu.global.u32 [%0], %1;"
                         :: "l"(&g_flags2[1][blockIdx.x * 32]), "r"(v) : "memory");
        }
    }
}

// ---------------- launch ----------------
extern "C" void kernel_launch(void* const* d_in, const int* in_sizes, int n_in,
                              void* d_out, int out_size) {
    const int*   in_seq = (const int*)  d_in[0];
    const float* h0     = (const float*)d_in[1];
    const float* c0     = (const float*)d_in[2];
    const float* table  = (const float*)d_in[3];
    const float* W1     = (const float*)d_in[4];
    const float* b1     = (const float*)d_in[5];
    const float* W2     = (const float*)d_in[6];
    const float* b2     = (const float*)d_in[7];
    const float* Wx     = (const float*)d_in[8];
    const float* Wh     = (const float*)d_in[9];
    const float* bias   = (const float*)d_in[10];

    float* out      = (float*)d_out;
    float* out_enc  = out;
    float* out_res9 = out + (size_t)BB * TT * HH;
    float* out_c    = out_res9 + BB * HH;

    const int lstm_smem = (32768 + 16 * 2 * 33) * 4;   // ~135.3 KB
    cudaFuncSetAttribute(lstm_kernel, cudaFuncAttributeMaxDynamicSharedMemorySize, lstm_smem);

    init_kernel<<<(BB * HH + 255) / 256, 256>>>(h0);
    embed_kernel<<<(int)(((long)M_ROWS * 75 + 255) / 256), 256>>>(in_seq, table);
    dim3 gg(G4 / 128, M_ROWS / 128);
    zx_gemm_tc<<<gg, 256>>>(Wx, bias);
    lstm_kernel<<<LC, 256, lstm_smem>>>(Wh, c0, h0, in_seq, out_enc, out_res9, out_c);  // #4 -> profiled
    conv1_kernel<<<BB * 8, 256>>>(W1, b1);
    conv2_kernel<<<BB, 512>>>(W2, b2);
    res9_kernel<<<(BB * HH + 255) / 256, 256>>>(out_res9);
}

// round 12
// speedup vs baseline: 1.6650x; 1.6650x over previous
#include <cuda_runtime.h>
#include <cstdint>

#define BB 64
#define TT 1024
#define EE 300
#define HH 512
#define G4 2048
#define M_ROWS (BB*TT)

// ---------------- scratch (device globals; no allocations) ----------------
__device__ float    g_out1[(size_t)M_ROWS * EE];   // embeddings
__device__ float    g_zx[(size_t)M_ROWS * G4];     // zx = out1@Wx + b
__device__ uint32_t g_hist[TT + 1][32768];         // h tf32 frag-major, FRESH slab per step
__device__ float    g_c1[BB * 8 * 256];            // conv1 window t=6..13
__device__ float    g_c2[BB * HH];                 // conv2 at t=9
__device__ unsigned g_flags[128 * 32];             // per-CTA barrier flags (128B stride)

// ---------------- tf32 mma.sync helpers ----------------
__device__ __forceinline__ uint32_t f2tf32(float f) {
    uint32_t r; asm("cvt.rna.tf32.f32 %0, %1;" : "=r"(r) : "f"(f)); return r;
}
__device__ __forceinline__ void mma16n8k8(float* d, const uint32_t* a, const uint32_t* b) {
    asm volatile("mma.sync.aligned.m16n8k8.row.col.f32.tf32.tf32.f32 "
        "{%0,%1,%2,%3}, {%4,%5,%6,%7}, {%8,%9}, {%0,%1,%2,%3};"
        : "+f"(d[0]), "+f"(d[1]), "+f"(d[2]), "+f"(d[3])
        : "r"(a[0]), "r"(a[1]), "r"(a[2]), "r"(a[3]), "r"(b[0]), "r"(b[1]));
}

// fragment-layout index for h value (b 0..63, col 0..511)  [proven round-8/9]
__device__ __forceinline__ int htf_idx(int b, int col) {
    int mtv = b >> 4, g2 = b & 7, hi = (b >> 3) & 1;
    int ks = col >> 3, khi = (col >> 2) & 1, kq = col & 3;
    return (((mtv * 64 + ks) << 7) + (g2 << 4) + (kq << 2) + khi * 2 + hi);
}

// ---------------- init: h0 -> g_hist[0], reset flags ----------
__global__ void init_kernel(const float* __restrict__ h0) {
    int i = blockIdx.x * blockDim.x + threadIdx.x;
    if (i < BB * HH) {
        int b = i >> 9, col = i & 511;
        g_hist[0][htf_idx(b, col)] = f2tf32(h0[i]);
    }
    if (i < 128 * 32) g_flags[i] = 0u;
}

// ---------------- embedding gather ----------------
__global__ void embed_kernel(const int* __restrict__ idx, const float* __restrict__ table) {
    long gid = (long)blockIdx.x * blockDim.x + threadIdx.x;
    const long total = (long)M_ROWS * 75;
    if (gid >= total) return;
    long r = gid / 75;
    int  e4 = (int)(gid % 75);
    int row = idx[r];
    ((float4*)g_out1)[r * 75 + e4] = ((const float4*)table)[(long)row * 75 + e4];
}

// ---------------- zx GEMM via mma.sync tf32 (proven) -------------
#define LDA 136
__global__ __launch_bounds__(256) void zx_gemm_tc(const float* __restrict__ Wx,
                                                  const float* __restrict__ bias) {
    __shared__ uint32_t As[32][LDA];
    __shared__ uint32_t Bs[32][LDA];

    const int tid  = threadIdx.x;
    const int wid  = tid >> 5;
    const int lane = tid & 31;
    const int gid  = lane >> 2;
    const int tig  = lane & 3;
    const int wm   = wid >> 2;
    const int wn   = wid & 3;
    const int bm = blockIdx.y * 128;
    const int bn = blockIdx.x * 128;

    float acc[4][4][4];
#pragma unroll
    for (int i = 0; i < 4; i++)
#pragma unroll
        for (int j = 0; j < 4; j++)
#pragma unroll
            for (int c = 0; c < 4; c++) acc[i][j][c] = 0.f;

    for (int k0 = 0; k0 < 320; k0 += 32) {
        {
            int row = tid >> 1;
            int kh  = (tid & 1) * 16;
            const float* src = &g_out1[(size_t)(bm + row) * EE + k0 + kh];
#pragma unroll
            for (int q = 0; q < 4; q++) {
                int kc = k0 + kh + q * 4;
                float4 v = make_float4(0.f, 0.f, 0.f, 0.f);
                if (kc + 3 < EE) v = *(const float4*)(src + q * 4);
                else {
                    if (kc + 0 < EE) v.x = src[q * 4 + 0];
                    if (kc + 1 < EE) v.y = src[q * 4 + 1];
                    if (kc + 2 < EE) v.z = src[q * 4 + 2];
                    if (kc + 3 < EE) v.w = src[q * 4 + 3];
                }
                As[kh + q * 4 + 0][row] = f2tf32(v.x);
                As[kh + q * 4 + 1][row] = f2tf32(v.y);
                As[kh + q * 4 + 2][row] = f2tf32(v.z);
                As[kh + q * 4 + 3][row] = f2tf32(v.w);
            }
        }
        {
            int k  = tid >> 3;
            int nq = (tid & 7) * 16;
#pragma unroll
            for (int q = 0; q < 4; q++) {
                float4 v = make_float4(0.f, 0.f, 0.f, 0.f);
                if (k0 + k < EE) v = *(const float4*)&Wx[(size_t)(k0 + k) * G4 + bn + nq + q * 4];
                Bs[k][nq + q * 4 + 0] = f2tf32(v.x);
                Bs[k][nq + q * 4 + 1] = f2tf32(v.y);
                Bs[k][nq + q * 4 + 2] = f2tf32(v.z);
                Bs[k][nq + q * 4 + 3] = f2tf32(v.w);
            }
        }
        __syncthreads();

#pragma unroll
        for (int s = 0; s < 4; s++) {
            const int ks = s * 8;
            uint32_t af[4][4], bf[4][2];
#pragma unroll
            for (int mt = 0; mt < 4; mt++) {
                int mb = wm * 64 + mt * 16 + gid;
                af[mt][0] = As[ks + tig][mb];
                af[mt][1] = As[ks + tig][mb + 8];
                af[mt][2] = As[ks + tig + 4][mb];
                af[mt][3] = As[ks + tig + 4][mb + 8];
            }
#pragma unroll
            for (int nt = 0; nt < 4; nt++) {
                int nb = wn * 32 + nt * 8 + gid;
                bf[nt][0] = Bs[ks + tig][nb];
                bf[nt][1] = Bs[ks + tig + 4][nb];
            }
#pragma unroll
            for (int mt = 0; mt < 4; mt++)
#pragma unroll
                for (int nt = 0; nt < 4; nt++)
                    mma16n8k8(acc[mt][nt], af[mt], bf[nt]);
        }
        __syncthreads();
    }

#pragma unroll
    for (int mt = 0; mt < 4; mt++) {
        int r0 = bm + wm * 64 + mt * 16 + gid;
#pragma unroll
        for (int nt = 0; nt < 4; nt++) {
            int ncol = bn + wn * 32 + nt * 8 + tig * 2;
            float2 bv = *(const float2*)&bias[ncol];
            float2 lo = make_float2(acc[mt][nt][0] + bv.x, acc[mt][nt][1] + bv.y);
            float2 hi = make_float2(acc[mt][nt][2] + bv.x, acc[mt][nt][3] + bv.y);
            *(float2*)&g_zx[(size_t)r0 * G4 + ncol] = lo;
            *(float2*)&g_zx[(size_t)(r0 + 8) * G4 + ncol] = hi;
        }
    }
}

// ---------------- conv1: 512 CTAs, one output t per CTA ----------------
__global__ __launch_bounds__(256) void conv1_kernel(const float* __restrict__ W1,
                                                    const float* __restrict__ b1) {
    int bb = blockIdx.x >> 3;
    int th = blockIdx.x & 7;
    __shared__ float xs[10 * EE];
    int tid = threadIdx.x;
    for (int i = tid; i < 10 * EE; i += 256) {
        int rt = i / EE, e = i % EE;
        xs[rt * EE + e] = g_out1[((long)(bb * TT) + 2 + th + rt) * EE + e];
    }
    __syncthreads();
    int m = tid;
    float acc = 0.f;
#pragma unroll 5
    for (int i = 0; i < 10 * EE; i++)
        acc += xs[i] * W1[(size_t)i * 256 + m];
    float v = acc + b1[m];
    v = v > 0.f ? v : 0.f;
    g_c1[(bb * 8 + th) * 256 + m] = v;
}

// ---------------- conv2 at t=9 ----------------
__global__ __launch_bounds__(512) void conv2_kernel(const float* __restrict__ W2,
                                                    const float* __restrict__ b2) {
    int bb = blockIdx.x;
    __shared__ float cs[8 * 256];
    int tid = threadIdx.x;
    for (int i = tid; i < 2048; i += 512) cs[i] = g_c1[bb * 2048 + i];
    __syncthreads();
    int n = tid;
    float acc = 0.f;
#pragma unroll 4
    for (int i = 0; i < 2048; i++)
        acc += cs[i] * W2[(size_t)i * HH + n];
    float v = acc + b2[n];
    v = v > 0.f ? v : 0.f;
    g_c2[bb * HH + n] = v;
}

// ---------------- res9 add ----------------
__global__ void res9_kernel(float* __restrict__ out_res9) {
    int i = blockIdx.x * blockDim.x + threadIdx.x;
    if (i < BB * HH) out_res9[i] += g_c2[i];
}

// ---------------- persistent masked LSTM: direct-LDG tensor recurrence -----
// h(t) lives in a FRESH global slab per step (g_hist[t]), tf32 fragment-major.
// A-fragments stream straight from global into mma.sync via an 8-deep
// prefetch ring — no SMEM staging, no named barriers; L2 broadcast overlaps
// the MMA issue stream. 8 warps = mt(4) x nt(2), full K per warp.
#define LC 128

__device__ __forceinline__ float sigf(float x) { return 1.f / (1.f + __expf(-x)); }

__global__ __launch_bounds__(256, 1) void lstm_kernel(const float* __restrict__ Wh,
                                                      const float* __restrict__ c0,
                                                      const float* __restrict__ h0,
                                                      const int* __restrict__ in_seq,
                                                      float* __restrict__ out_enc,
                                                      float* __restrict__ out_res9,
                                                      float* __restrict__ out_c) {
    __shared__ float red[16 * 66];
    __shared__ float hstage[256];

    const int tid  = threadIdx.x;
    const int warp = tid >> 5;
    const int lane = tid & 31;
    const int gid  = lane >> 2;
    const int tig  = lane & 3;
    const int mt   = warp >> 1;
    const int nt   = warp & 1;
    const int b    = tid & 63;
    const int jc   = tid >> 6;
    const int j0   = blockIdx.x * 4;
    const int col  = j0 + jc;
    const int my_idx = htf_idx(b, col);

    // ---- Wh fragments -> registers (loop-invariant), col c = g*4 + jj ----
    uint32_t bfr[64][2];
    {
        int c  = nt * 8 + gid;
        int g  = c >> 2, jj = c & 3;
        int wcol = j0 + jj + g * 512;
#pragma unroll 64
        for (int ks = 0; ks < 64; ks++) {
            bfr[ks][0] = f2tf32(Wh[(size_t)(ks * 8 + tig) * G4 + wcol]);
            bfr[ks][1] = f2tf32(Wh[(size_t)(ks * 8 + tig + 4) * G4 + wcol]);
        }
    }

    float creg = c0[b * HH + col];
    float hreg = h0[b * HH + col];

    // initial zx/mask prefetch (t=0)
    size_t zb = ((size_t)b * TT) * G4 + col;
    float zr0 = __ldg(&g_zx[zb]);
    float zr1 = __ldg(&g_zx[zb + 512]);
    float zr2 = __ldg(&g_zx[zb + 1024]);
    float zr3 = __ldg(&g_zx[zb + 1536]);
    int   mreg = in_seq[b * TT];
    __syncthreads();

    for (int t = 0; t < TT; t++) {
        // ---- wait for step-t h data (release by all CTAs at t-1) ----
        if (warp == 0 && t > 0) {
            const unsigned tgt = (unsigned)t;
            volatile unsigned* vf = g_flags;
            bool ok;
            do {
                unsigned v0 = vf[lane * 32];
                unsigned v1 = vf[(lane + 32) * 32];
                unsigned v2 = vf[(lane + 64) * 32];
                unsigned v3 = vf[(lane + 96) * 32];
                ok = (v0 >= tgt) && (v1 >= tgt) && (v2 >= tgt) && (v3 >= tgt);
            } while (!__all_sync(0xffffffffu, ok));
            asm volatile("fence.acq_rel.gpu;" ::: "memory");
        }
        __syncthreads();

        // ---- MMA: A-frags streamed from global (fresh addresses -> L1-safe) ----
        float acc[4] = {0.f, 0.f, 0.f, 0.f};
        {
            const uint4* hsrc = (const uint4*)(g_hist[t] + mt * 8192) + lane;
            uint4 ab[8];
#pragma unroll
            for (int p = 0; p < 8; p++) ab[p] = __ldg(hsrc + p * 32);
#pragma unroll 64
            for (int ks = 0; ks < 64; ks++) {
                uint32_t af[4];
                *(uint4*)af = ab[ks & 7];
                if (ks < 56) ab[ks & 7] = __ldg(hsrc + (ks + 8) * 32);
                mma16n8k8(acc, af, bfr[ks]);
            }
        }

        // ---- funnel acc -> red[c][b] ----
        {
            int c0i = nt * 8 + tig * 2;
            int r0  = mt * 16 + gid;
            red[(c0i    ) * 66 + r0]     = acc[0];
            red[(c0i + 1) * 66 + r0]     = acc[1];
            red[(c0i    ) * 66 + r0 + 8] = acc[2];
            red[(c0i + 1) * 66 + r0 + 8] = acc[3];
        }
        __syncthreads();

        // ---- gates: one (b, col) per thread; fresh-slab tf32 h store ----
        {
            float z0 = zr0 + red[(0 * 4 + jc) * 66 + b];
            float z1 = zr1 + red[(1 * 4 + jc) * 66 + b];
            float z2 = zr2 + red[(2 * 4 + jc) * 66 + b];
            float z3 = zr3 + red[(3 * 4 + jc) * 66 + b];
            float cn = sigf(z1) * creg + sigf(z0) * tanhf(z2);
            float hn = sigf(z3) * tanhf(cn);
            if (mreg == 0) { hn = hreg; cn = creg; }    // masked: carry state
            creg = cn; hreg = hn;
            hstage[b * 4 + jc] = hn;
            __stcg(&g_hist[t + 1][my_idx], f2tf32(hn));
            if (t == 9)      out_res9[b * HH + col] = hn;
            if (t == TT - 1) out_c[b * HH + col] = cn;
        }
        __syncthreads();

        // ---- release flag EARLY (h stores are ordered by release) ----
        if (tid == 0) {
            unsigned v = (unsigned)(t + 1);
            asm volatile("st.release.gpu.global.u32 [%0], %1;"
                         :: "l"(&g_flags[blockIdx.x * 32]), "r"(v) : "memory");
        }

        // ---- out_enc store + next-step zx prefetch (overlaps peers' polls) ----
        if (tid < 64) {
            float4 hv4 = *(const float4*)&hstage[tid * 4];
            *(float4*)&out_enc[((size_t)tid * TT + t) * HH + j0] = hv4;
        }
        if (t + 1 < TT) {
            zb = ((size_t)b * TT + (t + 1)) * G4 + col;
            zr0 = __ldg(&g_zx[zb]);
            zr1 = __ldg(&g_zx[zb + 512]);
            zr2 = __ldg(&g_zx[zb + 1024]);
            zr3 = __ldg(&g_zx[zb + 1536]);
            mreg = in_seq[b * TT + t + 1];
        }
    }
}

// ---------------- launch ----------------
extern "C" void kernel_launch(void* const* d_in, const int* in_sizes, int n_in,
                              void* d_out, int out_size) {
    const int*   in_seq = (const int*)  d_in[0];
    const float* h0     = (const float*)d_in[1];
    const float* c0     = (const float*)d_in[2];
    const float* table  = (const float*)d_in[3];
    const float* W1     = (const float*)d_in[4];
    const float* b1     = (const float*)d_in[5];
    const float* W2     = (const float*)d_in[6];
    const float* b2     = (const float*)d_in[7];
    const float* Wx     = (const float*)d_in[8];
    const float* Wh     = (const float*)d_in[9];
    const float* bias   = (const float*)d_in[10];

    float* out      = (float*)d_out;
    float* out_enc  = out;
    float* out_res9 = out + (size_t)BB * TT * HH;
    float* out_c    = out_res9 + BB * HH;

    init_kernel<<<(BB * HH + 255) / 256, 256>>>(h0);
    embed_kernel<<<(int)(((long)M_ROWS * 75 + 255) / 256), 256>>>(in_seq, table);
    dim3 gg(G4 / 128, M_ROWS / 128);
    zx_gemm_tc<<<gg, 256>>>(Wx, bias);
    lstm_kernel<<<LC, 256>>>(Wh, c0, h0, in_seq, out_enc, out_res9, out_c);  // #4 -> profiled
    conv1_kernel<<<BB * 8, 256>>>(W1, b1);
    conv2_kernel<<<BB, 512>>>(W2, b2);
    res9_kernel<<<(BB * HH + 255) / 256, 256>>>(out_res9);
}

// round 13
// speedup vs baseline: 1.8610x; 1.1177x over previous
#include <cuda_runtime.h>
#include <cstdint>

#define BB 64
#define TT 1024
#define EE 300
#define HH 512
#define G4 2048
#define M_ROWS (BB*TT)

// ---------------- scratch (device globals; no allocations) ----------------
__device__ float    g_out1[(size_t)M_ROWS * EE];   // embeddings
__device__ float    g_zx[(size_t)M_ROWS * G4];     // zx = out1@Wx + b
__device__ uint32_t g_hist[TT + 1][32768];         // h tf32 frag-major, FRESH slab per step
__device__ float    g_c1[BB * 8 * 256];            // conv1 window t=6..13
__device__ float    g_c2[BB * HH];                 // conv2 at t=9
__device__ unsigned g_flags[128 * 32];             // per-CTA barrier flags (128B stride)

// ---------------- tf32 mma.sync helpers ----------------
__device__ __forceinline__ uint32_t f2tf32(float f) {
    uint32_t r; asm("cvt.rna.tf32.f32 %0, %1;" : "=r"(r) : "f"(f)); return r;
}
__device__ __forceinline__ void mma16n8k8(float* d, const uint32_t* a, const uint32_t* b) {
    asm volatile("mma.sync.aligned.m16n8k8.row.col.f32.tf32.tf32.f32 "
        "{%0,%1,%2,%3}, {%4,%5,%6,%7}, {%8,%9}, {%0,%1,%2,%3};"
        : "+f"(d[0]), "+f"(d[1]), "+f"(d[2]), "+f"(d[3])
        : "r"(a[0]), "r"(a[1]), "r"(a[2]), "r"(a[3]), "r"(b[0]), "r"(b[1]));
}

// fragment-layout index for h value (b 0..63, col 0..511)  [proven round-8/9]
__device__ __forceinline__ int htf_idx(int b, int col) {
    int mtv = b >> 4, g2 = b & 7, hi = (b >> 3) & 1;
    int ks = col >> 3, khi = (col >> 2) & 1, kq = col & 3;
    return (((mtv * 64 + ks) << 7) + (g2 << 4) + (kq << 2) + khi * 2 + hi);
}

// ---------------- init: h0 -> g_hist[0], reset flags ----------
__global__ void init_kernel(const float* __restrict__ h0) {
    int i = blockIdx.x * blockDim.x + threadIdx.x;
    if (i < BB * HH) {
        int b = i >> 9, col = i & 511;
        g_hist[0][htf_idx(b, col)] = f2tf32(h0[i]);
    }
    if (i < 128 * 32) g_flags[i] = 0u;
}

// ---------------- embedding gather ----------------
__global__ void embed_kernel(const int* __restrict__ idx, const float* __restrict__ table) {
    long gid = (long)blockIdx.x * blockDim.x + threadIdx.x;
    const long total = (long)M_ROWS * 75;
    if (gid >= total) return;
    long r = gid / 75;
    int  e4 = (int)(gid % 75);
    int row = idx[r];
    ((float4*)g_out1)[r * 75 + e4] = ((const float4*)table)[(long)row * 75 + e4];
}

// ---------------- zx GEMM via mma.sync tf32 (proven) -------------
#define LDA 136
__global__ __launch_bounds__(256) void zx_gemm_tc(const float* __restrict__ Wx,
                                                  const float* __restrict__ bias) {
    __shared__ uint32_t As[32][LDA];
    __shared__ uint32_t Bs[32][LDA];

    const int tid  = threadIdx.x;
    const int wid  = tid >> 5;
    const int lane = tid & 31;
    const int gid  = lane >> 2;
    const int tig  = lane & 3;
    const int wm   = wid >> 2;
    const int wn   = wid & 3;
    const int bm = blockIdx.y * 128;
    const int bn = blockIdx.x * 128;

    float acc[4][4][4];
#pragma unroll
    for (int i = 0; i < 4; i++)
#pragma unroll
        for (int j = 0; j < 4; j++)
#pragma unroll
            for (int c = 0; c < 4; c++) acc[i][j][c] = 0.f;

    for (int k0 = 0; k0 < 320; k0 += 32) {
        {
            int row = tid >> 1;
            int kh  = (tid & 1) * 16;
            const float* src = &g_out1[(size_t)(bm + row) * EE + k0 + kh];
#pragma unroll
            for (int q = 0; q < 4; q++) {
                int kc = k0 + kh + q * 4;
                float4 v = make_float4(0.f, 0.f, 0.f, 0.f);
                if (kc + 3 < EE) v = *(const float4*)(src + q * 4);
                else {
                    if (kc + 0 < EE) v.x = src[q * 4 + 0];
                    if (kc + 1 < EE) v.y = src[q * 4 + 1];
                    if (kc + 2 < EE) v.z = src[q * 4 + 2];
                    if (kc + 3 < EE) v.w = src[q * 4 + 3];
                }
                As[kh + q * 4 + 0][row] = f2tf32(v.x);
                As[kh + q * 4 + 1][row] = f2tf32(v.y);
                As[kh + q * 4 + 2][row] = f2tf32(v.z);
                As[kh + q * 4 + 3][row] = f2tf32(v.w);
            }
        }
        {
            int k  = tid >> 3;
            int nq = (tid & 7) * 16;
#pragma unroll
            for (int q = 0; q < 4; q++) {
                float4 v = make_float4(0.f, 0.f, 0.f, 0.f);
                if (k0 + k < EE) v = *(const float4*)&Wx[(size_t)(k0 + k) * G4 + bn + nq + q * 4];
                Bs[k][nq + q * 4 + 0] = f2tf32(v.x);
                Bs[k][nq + q * 4 + 1] = f2tf32(v.y);
                Bs[k][nq + q * 4 + 2] = f2tf32(v.z);
                Bs[k][nq + q * 4 + 3] = f2tf32(v.w);
            }
        }
        __syncthreads();

#pragma unroll
        for (int s = 0; s < 4; s++) {
            const int ks = s * 8;
            uint32_t af[4][4], bf[4][2];
#pragma unroll
            for (int mt = 0; mt < 4; mt++) {
                int mb = wm * 64 + mt * 16 + gid;
                af[mt][0] = As[ks + tig][mb];
                af[mt][1] = As[ks + tig][mb + 8];
                af[mt][2] = As[ks + tig + 4][mb];
                af[mt][3] = As[ks + tig + 4][mb + 8];
            }
#pragma unroll
            for (int nt = 0; nt < 4; nt++) {
                int nb = wn * 32 + nt * 8 + gid;
                bf[nt][0] = Bs[ks + tig][nb];
                bf[nt][1] = Bs[ks + tig + 4][nb];
            }
#pragma unroll
            for (int mt = 0; mt < 4; mt++)
#pragma unroll
                for (int nt = 0; nt < 4; nt++)
                    mma16n8k8(acc[mt][nt], af[mt], bf[nt]);
        }
        __syncthreads();
    }

#pragma unroll
    for (int mt = 0; mt < 4; mt++) {
        int r0 = bm + wm * 64 + mt * 16 + gid;
#pragma unroll
        for (int nt = 0; nt < 4; nt++) {
            int ncol = bn + wn * 32 + nt * 8 + tig * 2;
            float2 bv = *(const float2*)&bias[ncol];
            float2 lo = make_float2(acc[mt][nt][0] + bv.x, acc[mt][nt][1] + bv.y);
            float2 hi = make_float2(acc[mt][nt][2] + bv.x, acc[mt][nt][3] + bv.y);
            *(float2*)&g_zx[(size_t)r0 * G4 + ncol] = lo;
            *(float2*)&g_zx[(size_t)(r0 + 8) * G4 + ncol] = hi;
        }
    }
}

// ---------------- conv1: 512 CTAs, one output t per CTA ----------------
__global__ __launch_bounds__(256) void conv1_kernel(const float* __restrict__ W1,
                                                    const float* __restrict__ b1) {
    int bb = blockIdx.x >> 3;
    int th = blockIdx.x & 7;
    __shared__ float xs[10 * EE];
    int tid = threadIdx.x;
    for (int i = tid; i < 10 * EE; i += 256) {
        int rt = i / EE, e = i % EE;
        xs[rt * EE + e] = g_out1[((long)(bb * TT) + 2 + th + rt) * EE + e];
    }
    __syncthreads();
    int m = tid;
    float acc = 0.f;
#pragma unroll 5
    for (int i = 0; i < 10 * EE; i++)
        acc += xs[i] * W1[(size_t)i * 256 + m];
    float v = acc + b1[m];
    v = v > 0.f ? v : 0.f;
    g_c1[(bb * 8 + th) * 256 + m] = v;
}

// ---------------- conv2 at t=9 ----------------
__global__ __launch_bounds__(512) void conv2_kernel(const float* __restrict__ W2,
                                                    const float* __restrict__ b2) {
    int bb = blockIdx.x;
    __shared__ float cs[8 * 256];
    int tid = threadIdx.x;
    for (int i = tid; i < 2048; i += 512) cs[i] = g_c1[bb * 2048 + i];
    __syncthreads();
    int n = tid;
    float acc = 0.f;
#pragma unroll 4
    for (int i = 0; i < 2048; i++)
        acc += cs[i] * W2[(size_t)i * HH + n];
    float v = acc + b2[n];
    v = v > 0.f ? v : 0.f;
    g_c2[bb * HH + n] = v;
}

// ---------------- res9 add ----------------
__global__ void res9_kernel(float* __restrict__ out_res9) {
    int i = blockIdx.x * blockDim.x + threadIdx.x;
    if (i < BB * HH) out_res9[i] += g_c2[i];
}

// ---------------- persistent masked LSTM: direct-LDG, A-dedup warp layout ---
// 8 warps = mt(4) x kh(2): each warp owns m16 batch rows and a K-half (256),
// computing BOTH n8 tiles from one A-fragment stream -> A-LDG traffic halves
// to the 128 KB/CTA/step floor. Partial sums over kh reduced in SMEM.
#define LC 128

__device__ __forceinline__ float sigf(float x) { return 1.f / (1.f + __expf(-x)); }

__global__ __launch_bounds__(256, 1) void lstm_kernel(const float* __restrict__ Wh,
                                                      const float* __restrict__ c0,
                                                      const float* __restrict__ h0,
                                                      const int* __restrict__ in_seq,
                                                      float* __restrict__ out_enc,
                                                      float* __restrict__ out_res9,
                                                      float* __restrict__ out_c) {
    __shared__ float red[16 * 2 * 66];     // [col(16)][kh(2)][row(66 stride)]
    __shared__ float hstage[256];

    const int tid  = threadIdx.x;
    const int warp = tid >> 5;
    const int lane = tid & 31;
    const int gid  = lane >> 2;
    const int tig  = lane & 3;
    const int mt   = warp >> 1;            // 0..3  batch 16-row tile
    const int kh   = warp & 1;             // 0..1  K-half
    const int b    = tid & 63;
    const int jc   = tid >> 6;
    const int j0   = blockIdx.x * 4;
    const int col  = j0 + jc;
    const int my_idx = htf_idx(b, col);

    // ---- Wh fragments -> registers: both n8 tiles, own K-half ----
    uint32_t bfr[2][32][2];
    {
        const int kb = kh * 256;
#pragma unroll
        for (int nt = 0; nt < 2; nt++) {
            int c  = nt * 8 + gid;
            int g  = c >> 2, jj = c & 3;
            int wcol = j0 + jj + g * 512;
#pragma unroll 32
            for (int ks = 0; ks < 32; ks++) {
                bfr[nt][ks][0] = f2tf32(Wh[(size_t)(kb + ks * 8 + tig) * G4 + wcol]);
                bfr[nt][ks][1] = f2tf32(Wh[(size_t)(kb + ks * 8 + tig + 4) * G4 + wcol]);
            }
        }
    }

    float creg = c0[b * HH + col];
    float hreg = h0[b * HH + col];

    // initial zx/mask prefetch (t=0)
    size_t zb = ((size_t)b * TT) * G4 + col;
    float zr0 = __ldg(&g_zx[zb]);
    float zr1 = __ldg(&g_zx[zb + 512]);
    float zr2 = __ldg(&g_zx[zb + 1024]);
    float zr3 = __ldg(&g_zx[zb + 1536]);
    int   mreg = in_seq[b * TT];
    __syncthreads();

    for (int t = 0; t < TT; t++) {
        // ---- wait for step-t h data (release by all CTAs at t-1) ----
        if (warp == 0 && t > 0) {
            const unsigned tgt = (unsigned)t;
            volatile unsigned* vf = g_flags;
            bool ok;
            do {
                unsigned v0 = vf[lane * 32];
                unsigned v1 = vf[(lane + 32) * 32];
                unsigned v2 = vf[(lane + 64) * 32];
                unsigned v3 = vf[(lane + 96) * 32];
                ok = (v0 >= tgt) && (v1 >= tgt) && (v2 >= tgt) && (v3 >= tgt);
            } while (!__all_sync(0xffffffffu, ok));
            asm volatile("fence.acq_rel.gpu;" ::: "memory");
        }
        __syncthreads();

        // ---- MMA: A-frags streamed from global, one K-half, both n-tiles ----
        float acc0[4] = {0.f, 0.f, 0.f, 0.f};
        float acc1[4] = {0.f, 0.f, 0.f, 0.f};
        {
            const uint4* hsrc = (const uint4*)(g_hist[t] + mt * 8192 + kh * 4096) + lane;
            uint4 ab[8];
#pragma unroll
            for (int p = 0; p < 8; p++) ab[p] = __ldg(hsrc + p * 32);
#pragma unroll 32
            for (int ks = 0; ks < 32; ks++) {
                uint32_t af[4];
                *(uint4*)af = ab[ks & 7];
                if (ks < 24) ab[ks & 7] = __ldg(hsrc + (ks + 8) * 32);
                mma16n8k8(acc0, af, bfr[0][ks]);
                mma16n8k8(acc1, af, bfr[1][ks]);
            }
        }

        // ---- funnel partials -> red[col][kh][row] ----
        {
            int r0 = mt * 16 + gid;
#pragma unroll
            for (int nt = 0; nt < 2; nt++) {
                const float* a = nt ? acc1 : acc0;
                int c0i = nt * 8 + tig * 2;
                red[((c0i    ) * 2 + kh) * 66 + r0]     = a[0];
                red[((c0i + 1) * 2 + kh) * 66 + r0]     = a[1];
                red[((c0i    ) * 2 + kh) * 66 + r0 + 8] = a[2];
                red[((c0i + 1) * 2 + kh) * 66 + r0 + 8] = a[3];
            }
        }
        __syncthreads();

        // ---- gates: one (b, col) per thread; sum kh partials ----
        {
            float z0 = zr0 + red[((0 * 4 + jc) * 2) * 66 + b] + red[((0 * 4 + jc) * 2 + 1) * 66 + b];
            float z1 = zr1 + red[((1 * 4 + jc) * 2) * 66 + b] + red[((1 * 4 + jc) * 2 + 1) * 66 + b];
            float z2 = zr2 + red[((2 * 4 + jc) * 2) * 66 + b] + red[((2 * 4 + jc) * 2 + 1) * 66 + b];
            float z3 = zr3 + red[((3 * 4 + jc) * 2) * 66 + b] + red[((3 * 4 + jc) * 2 + 1) * 66 + b];
            float cn = sigf(z1) * creg + sigf(z0) * tanhf(z2);
            float hn = sigf(z3) * tanhf(cn);
            if (mreg == 0) { hn = hreg; cn = creg; }    // masked: carry state
            creg = cn; hreg = hn;
            hstage[b * 4 + jc] = hn;
            __stcg(&g_hist[t + 1][my_idx], f2tf32(hn));
            if (t == 9)      out_res9[b * HH + col] = hn;
            if (t == TT - 1) out_c[b * HH + col] = cn;
        }
        __syncthreads();

        // ---- release flag EARLY (h stores are ordered by release) ----
        if (tid == 0) {
            unsigned v = (unsigned)(t + 1);
            asm volatile("st.release.gpu.global.u32 [%0], %1;"
                         :: "l"(&g_flags[blockIdx.x * 32]), "r"(v) : "memory");
        }

        // ---- out_enc store + next-step zx prefetch (overlaps peers' polls) ----
        if (tid < 64) {
            float4 hv4 = *(const float4*)&hstage[tid * 4];
            *(float4*)&out_enc[((size_t)tid * TT + t) * HH + j0] = hv4;
        }
        if (t + 1 < TT) {
            zb = ((size_t)b * TT + (t + 1)) * G4 + col;
            zr0 = __ldg(&g_zx[zb]);
            zr1 = __ldg(&g_zx[zb + 512]);
            zr2 = __ldg(&g_zx[zb + 1024]);
            zr3 = __ldg(&g_zx[zb + 1536]);
            mreg = in_seq[b * TT + t + 1];
        }
    }
}

// ---------------- launch ----------------
extern "C" void kernel_launch(void* const* d_in, const int* in_sizes, int n_in,
                              void* d_out, int out_size) {
    const int*   in_seq = (const int*)  d_in[0];
    const float* h0     = (const float*)d_in[1];
    const float* c0     = (const float*)d_in[2];
    const float* table  = (const float*)d_in[3];
    const float* W1     = (const float*)d_in[4];
    const float* b1     = (const float*)d_in[5];
    const float* W2     = (const float*)d_in[6];
    const float* b2     = (const float*)d_in[7];
    const float* Wx     = (const float*)d_in[8];
    const float* Wh     = (const float*)d_in[9];
    const float* bias   = (const float*)d_in[10];

    float* out      = (float*)d_out;
    float* out_enc  = out;
    float* out_res9 = out + (size_t)BB * TT * HH;
    float* out_c    = out_res9 + BB * HH;

    init_kernel<<<(BB * HH + 255) / 256, 256>>>(h0);
    embed_kernel<<<(int)(((long)M_ROWS * 75 + 255) / 256), 256>>>(in_seq, table);
    dim3 gg(G4 / 128, M_ROWS / 128);
    zx_gemm_tc<<<gg, 256>>>(Wx, bias);
    lstm_kernel<<<LC, 256>>>(Wh, c0, h0, in_seq, out_enc, out_res9, out_c);  // #4 -> profiled
    conv1_kernel<<<BB * 8, 256>>>(W1, b1);
    conv2_kernel<<<BB, 512>>>(W2, b2);
    res9_kernel<<<(BB * HH + 255) / 256, 256>>>(out_res9);
}